// round 8
// baseline (speedup 1.0000x reference)
#include <cuda_runtime.h>
#include <cuda_fp16.h>
#include <cstdint>

#define F_DIM    48
#define CHUNKS   12            // 48 floats = 12 float4 per node (output side)
#define N_NODES  100000
#define N_EDGES  1600000

#define SCAN_TPB   1024
#define SCAN_ELEMS (N_NODES + 1)                                // 100001
#define SCAN_NBLK  ((SCAN_ELEMS + SCAN_TPB - 1) / SCAN_TPB)     // 98

// ---------------------------------------------------------------------------
// Scratch (__device__ globals — no allocation)
// ---------------------------------------------------------------------------
__device__ int    g_count[N_NODES + 1];   // histogram -> CSR offsets -> ends
__device__ int    g_blocksums[SCAN_NBLK];
__device__ int2   g_edge[N_EDGES];        // row-sorted {col, val-bits(f32)}
__device__ __half g_xh[N_NODES * F_DIM];  // x quantized to fp16 (9.6 MB)

// ---------------------------------------------------------------------------
// 1. prologue: convert x -> fp16 AND zero the histogram. One launch.
//    thread i: converts x4[i] (i < 1.2M) ; zeroes g_count[i] (i <= N_NODES)
// ---------------------------------------------------------------------------
__global__ __launch_bounds__(256)
void prologue_kernel(const float4* __restrict__ x4, int n4) {
    int i = blockIdx.x * blockDim.x + threadIdx.x;
    if (i < n4) {
        float4 v = x4[i];
        __half2 h0 = __floats2half2_rn(v.x, v.y);
        __half2 h1 = __floats2half2_rn(v.z, v.w);
        uint2 packed;
        packed.x = *reinterpret_cast<unsigned int*>(&h0);
        packed.y = *reinterpret_cast<unsigned int*>(&h1);
        *reinterpret_cast<uint2*>(g_xh + (size_t)i * 4) = packed;
    }
    if (i <= N_NODES) g_count[i] = 0;
}

// ---------------------------------------------------------------------------
// 2. histogram: fire-and-forget RED, 4 edges/thread (vector row load)
// ---------------------------------------------------------------------------
__global__ __launch_bounds__(256)
void hist_kernel(const int* __restrict__ rows, int nE) {
    int q = blockIdx.x * blockDim.x + threadIdx.x;
    int e = q * 4;
    if (e + 3 < nE) {
        int4 r = *reinterpret_cast<const int4*>(rows + e);
        atomicAdd(&g_count[r.x + 1], 1);
        atomicAdd(&g_count[r.y + 1], 1);
        atomicAdd(&g_count[r.z + 1], 1);
        atomicAdd(&g_count[r.w + 1], 1);
    } else {
        for (; e < nE; e++) atomicAdd(&g_count[__ldg(rows + e) + 1], 1);
    }
}

// ---------------------------------------------------------------------------
// 3a. block-local inclusive scan (1024 elems/block) + block sums
//     After full scan: g_count[n] = start offset of row n, g_count[N] = E.
// ---------------------------------------------------------------------------
__global__ __launch_bounds__(SCAN_TPB)
void scan1_kernel() {
    __shared__ int buf[2][SCAN_TPB];
    int t = threadIdx.x;
    int idx = blockIdx.x * SCAN_TPB + t;
    int v = (idx < SCAN_ELEMS) ? g_count[idx] : 0;
    int src = 0;
    buf[0][t] = v;
    __syncthreads();
    #pragma unroll
    for (int off = 1; off < SCAN_TPB; off <<= 1) {
        int val = buf[src][t];
        if (t >= off) val += buf[src][t - off];
        buf[src ^ 1][t] = val;
        src ^= 1;
        __syncthreads();
    }
    if (idx < SCAN_ELEMS) g_count[idx] = buf[src][t];
    if (t == SCAN_TPB - 1) g_blocksums[blockIdx.x] = buf[src][t];
}

// ---------------------------------------------------------------------------
// 3b. fixup: add prefix of block sums (uniform broadcast loop, <=97 iters)
// ---------------------------------------------------------------------------
__global__ __launch_bounds__(SCAN_TPB)
void scan2_kernel() {
    int t = threadIdx.x;
    int idx = blockIdx.x * SCAN_TPB + t;
    if (idx >= SCAN_ELEMS || blockIdx.x == 0) return;
    int base = 0;
    for (int b = 0; b < blockIdx.x; b++) base += __ldg(&g_blocksums[b]);
    g_count[idx] += base;
}

// ---------------------------------------------------------------------------
// 4. reorder: p = atomicAdd(&g_count[row], 1); 4 edges/thread for MLP.
//    After this kernel g_count[r] == end(r) == start(r+1).
// ---------------------------------------------------------------------------
__global__ __launch_bounds__(256)
void reorder_kernel(const int*   __restrict__ rows,
                    const int*   __restrict__ cols,
                    const float* __restrict__ vals, int nE) {
    int q = blockIdx.x * blockDim.x + threadIdx.x;
    int e = q * 4;
    if (e + 3 < nE) {
        int4   r  = *reinterpret_cast<const int4*>(rows + e);
        int4   cc = *reinterpret_cast<const int4*>(cols + e);
        float4 vv = *reinterpret_cast<const float4*>(vals + e);
        // 4 independent atomic chains in flight
        int p0 = atomicAdd(&g_count[r.x], 1);
        int p1 = atomicAdd(&g_count[r.y], 1);
        int p2 = atomicAdd(&g_count[r.z], 1);
        int p3 = atomicAdd(&g_count[r.w], 1);
        g_edge[p0] = make_int2(cc.x, __float_as_int(vv.x));
        g_edge[p1] = make_int2(cc.y, __float_as_int(vv.y));
        g_edge[p2] = make_int2(cc.z, __float_as_int(vv.z));
        g_edge[p3] = make_int2(cc.w, __float_as_int(vv.w));
    } else {
        for (; e < nE; e++) {
            int p = atomicAdd(&g_count[__ldg(rows + e)], 1);
            g_edge[p] = make_int2(__ldg(cols + e),
                                  __float_as_int(__ldg(vals + e)));
        }
    }
}

// ---------------------------------------------------------------------------
// 5. gather: 12 lanes per node; lane c owns features [4c, 4c+4).
//    Reads fp16 x (8B per edge per lane = half the fp32 traffic),
//    accumulates fp32, applies w once, single output write. No atomics.
//    start(n) = g_count[n-1] (post-reorder ends), end(n) = g_count[n].
// ---------------------------------------------------------------------------
__device__ __forceinline__ float4 load_x4h(int col, int c) {
    uint2 raw = *reinterpret_cast<const uint2*>(g_xh + (size_t)col * F_DIM + c * 4);
    __half2 h0 = *reinterpret_cast<__half2*>(&raw.x);
    __half2 h1 = *reinterpret_cast<__half2*>(&raw.y);
    float2 f0 = __half22float2(h0);
    float2 f1 = __half22float2(h1);
    return make_float4(f0.x, f0.y, f1.x, f1.y);
}

__global__ __launch_bounds__(256)
void gather_kernel(const float4* __restrict__ w4,
                   float4*       __restrict__ out4) {
    int gid = blockIdx.x * blockDim.x + threadIdx.x;
    int node = gid / CHUNKS;
    int c = gid - node * CHUNKS;
    if (node >= N_NODES) return;

    const int start = (node == 0) ? 0 : __ldg(&g_count[node - 1]);
    const int end   = __ldg(&g_count[node]);

    float4 acc = make_float4(0.f, 0.f, 0.f, 0.f);
    int e = start;
    for (; e + 3 < end; e += 4) {
        int2 m0 = __ldg(g_edge + e + 0);
        int2 m1 = __ldg(g_edge + e + 1);
        int2 m2 = __ldg(g_edge + e + 2);
        int2 m3 = __ldg(g_edge + e + 3);
        float4 a0 = load_x4h(m0.x, c);
        float4 a1 = load_x4h(m1.x, c);
        float4 a2 = load_x4h(m2.x, c);
        float4 a3 = load_x4h(m3.x, c);
        float v0 = __int_as_float(m0.y), v1 = __int_as_float(m1.y);
        float v2 = __int_as_float(m2.y), v3 = __int_as_float(m3.y);
        acc.x += v0 * a0.x + v1 * a1.x + v2 * a2.x + v3 * a3.x;
        acc.y += v0 * a0.y + v1 * a1.y + v2 * a2.y + v3 * a3.y;
        acc.z += v0 * a0.z + v1 * a1.z + v2 * a2.z + v3 * a3.z;
        acc.w += v0 * a0.w + v1 * a1.w + v2 * a2.w + v3 * a3.w;
    }
    for (; e < end; e++) {
        int2 m = __ldg(g_edge + e);
        float4 a = load_x4h(m.x, c);
        float v = __int_as_float(m.y);
        acc.x += v * a.x;
        acc.y += v * a.y;
        acc.z += v * a.z;
        acc.w += v * a.w;
    }

    float4 wv = __ldg(w4 + c);
    acc.x *= wv.x; acc.y *= wv.y; acc.z *= wv.z; acc.w *= wv.w;

    out4[(size_t)node * CHUNKS + c] = acc;
}

// ---------------------------------------------------------------------------
// Launch
// Inputs: 0 x[1,100000,48] f32 | 1 w[1,48] f32 | 2 rows[1.6M] i32
//         3 cols[1.6M] i32     | 4 vals[1.6M] f32
// Output: f32 [100000, 48]
// ---------------------------------------------------------------------------
extern "C" void kernel_launch(void* const* d_in, const int* in_sizes, int n_in,
                              void* d_out, int out_size) {
    const float* x    = (const float*)d_in[0];
    const float* w    = (const float*)d_in[1];
    const int*   rows = (const int*)  d_in[2];
    const int*   cols = (const int*)  d_in[3];
    const float* vals = (const float*)d_in[4];
    float*       out  = (float*)d_out;

    const int nE = in_sizes[2];

    // 1. prologue: x -> fp16 + zero histogram
    {
        int n4 = N_NODES * CHUNKS;                 // 1.2M float4 groups
        prologue_kernel<<<(n4 + 255) / 256, 256>>>((const float4*)x, n4);
    }
    // 2. histogram (fire-and-forget RED, 4 edges/thread)
    {
        int nq = (nE + 3) / 4;
        hist_kernel<<<(nq + 255) / 256, 256>>>(rows, nE);
    }
    // 3. scan
    scan1_kernel<<<SCAN_NBLK, SCAN_TPB>>>();
    scan2_kernel<<<SCAN_NBLK, SCAN_TPB>>>();
    // 4. reorder (atomic cursors on g_count, 4 edges/thread)
    {
        int nq = (nE + 3) / 4;
        reorder_kernel<<<(nq + 255) / 256, 256>>>(rows, cols, vals, nE);
    }
    // 5. gather (fp16 x, fp32 accumulate)
    {
        int n = N_NODES * CHUNKS;
        gather_kernel<<<(n + 255) / 256, 256>>>((const float4*)w,
                                                (float4*)out);
    }
}